// round 7
// baseline (speedup 1.0000x reference)
#include <cuda_runtime.h>

#define NN 524288
#define ROWS_PB 256
#define GRID (NN / ROWS_PB)   // 2048 blocks, 128 threads, 2 rows/thread
#define DD 64
#define HH 128
#define EE 8
#define AA 18
#define BN_EPS 1e-5f

typedef unsigned long long u64;

__device__ __forceinline__ u64 pk2(float lo, float hi) {
    u64 r; asm("mov.b64 %0,{%1,%2};" : "=l"(r) : "f"(lo), "f"(hi)); return r;
}
__device__ __forceinline__ void upk2(u64 v, float& lo, float& hi) {
    asm("mov.b64 {%0,%1},%2;" : "=f"(lo), "=f"(hi) : "l"(v));
}
__device__ __forceinline__ void ffma2(u64& d, u64 a, u64 b) {
    asm("fma.rn.f32x2 %0,%1,%2,%0;" : "+l"(d) : "l"(a), "l"(b));
}
__device__ __forceinline__ u64 add2(u64 a, u64 b) {
    u64 r; asm("add.rn.f32x2 %0,%1,%2;" : "=l"(r) : "l"(a), "l"(b)); return r;
}

// smem layout (floats):
//   w1s [0, 8192)        W1 row-major [H][D]
//   w2t [8192, 9216)     W2 transposed [H][E]
//   sbs [9216, 9472)     (scale,bias) interleaved per j
//   b2s [9472, 9488)
//   wes [9488, ...)      We flat, stride 1156/expert
#define WE_STRIDE 1156
#define SMEM_FLOATS (9488 + EE * WE_STRIDE)

__global__ __launch_bounds__(128, 3) void moe_fused(
    const float* __restrict__ X,  const float* __restrict__ W1, const float* __restrict__ b1,
    const float* __restrict__ gamma, const float* __restrict__ beta,
    const float* __restrict__ rmean, const float* __restrict__ rvar,
    const float* __restrict__ W2, const float* __restrict__ b2, const float* __restrict__ We,
    float* __restrict__ out, float* __restrict__ ret)
{
    extern __shared__ float sm[];
    float* w1s = sm;
    float* w2t = sm + 8192;
    float* sbs = sm + 9216;
    float* b2s = sm + 9472;
    float* wes = sm + 9488;

    const int tid = threadIdx.x;

    // ---- stage weights (128 threads) ----
    {   // W1: 2048 float4 linear copy
        const float4* src = (const float4*)W1;
        float4* dst = (float4*)w1s;
        #pragma unroll
        for (int i = 0; i < 16; i++) dst[tid + 128 * i] = src[tid + 128 * i];
    }
    {   // We: 8 x 288 float4, dst stride 289 float4
        const float4* src = (const float4*)We;
        float4* dst = (float4*)wes;
        #pragma unroll
        for (int i = 0; i < 18; i++) {
            int idx = tid + 128 * i;   // < 2304
            int e = idx / 288, r = idx % 288;
            dst[e * (WE_STRIDE / 4) + r] = src[idx];
        }
    }
    #pragma unroll
    for (int i = 0; i < 8; i++) {   // w2t[j*8+e] = W2[e*H+j]
        int idx = tid + 128 * i;
        int j = idx >> 3, e = idx & 7;
        w2t[idx] = W2[e * HH + j];
    }
    {
        int j = tid;
        float s = gamma[j] * rsqrtf(rvar[j] + BN_EPS);
        sbs[2 * j]     = s;
        sbs[2 * j + 1] = s * (b1[j] - rmean[j]) + beta[j];
    }
    if (tid < EE) b2s[tid] = b2[tid];
    __syncthreads();

    const int r0 = blockIdx.x * ROWS_PB + tid;
    const int r1 = r0 + 128;

    // ---- x for both rows, k-packed f32x2 (64 u64 = 128 regs) ----
    u64 xp0[32], xp1[32];
    {
        const ulonglong2* p0 = (const ulonglong2*)(X + (size_t)r0 * DD);
        const ulonglong2* p1 = (const ulonglong2*)(X + (size_t)r1 * DD);
        #pragma unroll
        for (int i = 0; i < 16; i++) {
            ulonglong2 t0 = p0[i]; xp0[2 * i] = t0.x; xp0[2 * i + 1] = t0.y;
            ulonglong2 t1 = p1[i]; xp1[2 * i] = t1.x; xp1[2 * i + 1] = t1.y;
        }
    }

    const u64 Z = pk2(0.f, 0.f);

    u64 lg0[4], lg1[4];
    #pragma unroll
    for (int k = 0; k < 4; k++) {
        u64 b2p = pk2(b2s[2 * k], b2s[2 * k + 1]);
        lg0[k] = b2p; lg1[k] = b2p;
    }

    // ---- gating: shared W1 loads serve both rows; 2 accum chains/row ----
    #pragma unroll 1
    for (int j = 0; j < HH; j++) {
        const ulonglong2* pw = (const ulonglong2*)(w1s + j * DD);
        u64 a0 = Z, a1 = Z;        // row 0
        u64 c0 = Z, c1 = Z;        // row 1
        #pragma unroll
        for (int i = 0; i < 16; i++) {
            ulonglong2 w = pw[i];            // floats [4i, 4i+4)
            ffma2(a0, w.x, xp0[2 * i]);
            ffma2(c0, w.x, xp1[2 * i]);
            ffma2(a1, w.y, xp0[2 * i + 1]);
            ffma2(c1, w.y, xp1[2 * i + 1]);
        }
        u64 s0 = add2(a0, a1);
        u64 s1 = add2(c0, c1);
        float e0, f0, e1, f1;
        upk2(s0, e0, f0); upk2(s1, e1, f1);
        float dot0 = e0 + f0, dot1 = e1 + f1;

        float2 sb = ((const float2*)sbs)[j];
        float y0 = fmaxf(fmaf(sb.x, dot0, sb.y), 0.f);
        float y1 = fmaxf(fmaf(sb.x, dot1, sb.y), 0.f);
        u64 yb0 = pk2(y0, y0), yb1 = pk2(y1, y1);

        const ulonglong2* pw2 = (const ulonglong2*)(w2t + j * EE);
        ulonglong2 q0 = pw2[0], q1 = pw2[1];
        ffma2(lg0[0], q0.x, yb0);
        ffma2(lg1[0], q0.x, yb1);
        ffma2(lg0[1], q0.y, yb0);
        ffma2(lg1[1], q0.y, yb1);
        ffma2(lg0[2], q1.x, yb0);
        ffma2(lg1[2], q1.x, yb1);
        ffma2(lg0[3], q1.y, yb0);
        ffma2(lg1[3], q1.y, yb1);
    }

    // ---- per row: argmax + one-hot + expert GEMV ----
    #pragma unroll 1
    for (int rr = 0; rr < 2; rr++) {
        const u64* lg  = rr ? lg1 : lg0;
        const u64* xp  = rr ? xp1 : xp0;
        const int row  = rr ? r1 : r0;

        float lf[8];
        upk2(lg[0], lf[0], lf[1]);
        upk2(lg[1], lf[2], lf[3]);
        upk2(lg[2], lf[4], lf[5]);
        upk2(lg[3], lf[6], lf[7]);
        int best = 0; float bv = lf[0];
        #pragma unroll
        for (int e = 1; e < 8; e++) if (lf[e] > bv) { bv = lf[e]; best = e; }

        float rv[8];
        #pragma unroll
        for (int e = 0; e < 8; e++) rv[e] = (e == best) ? 1.0f : 0.0f;
        float4* pr = (float4*)(ret + (size_t)row * EE);
        pr[0] = make_float4(rv[0], rv[1], rv[2], rv[3]);
        pr[1] = make_float4(rv[4], rv[5], rv[6], rv[7]);

        const ulonglong2* pe = (const ulonglong2*)(wes + best * WE_STRIDE);
        float* orow = out + (size_t)row * AA;
        #pragma unroll
        for (int a = 0; a < AA; a++) {
            u64 a0 = Z, a1 = Z, a2 = Z, a3 = Z;
            #pragma unroll
            for (int m = 0; m < 8; m++) {
                ulonglong2 w = pe[a * 16 + 2 * m];
                ulonglong2 v = pe[a * 16 + 2 * m + 1];
                ffma2(a0, w.x, xp[4 * m + 0]);
                ffma2(a1, w.y, xp[4 * m + 1]);
                ffma2(a2, v.x, xp[4 * m + 2]);
                ffma2(a3, v.y, xp[4 * m + 3]);
            }
            u64 s = add2(add2(a0, a1), add2(a2, a3));
            float lo, hi; upk2(s, lo, hi);
            orow[a] = lo + hi;
        }
    }
}

extern "C" void kernel_launch(void* const* d_in, const int* in_sizes, int n_in,
                              void* d_out, int out_size) {
    const float* X     = (const float*)d_in[0];
    const float* W1    = (const float*)d_in[1];
    const float* b1    = (const float*)d_in[2];
    const float* gamma = (const float*)d_in[3];
    const float* beta  = (const float*)d_in[4];
    const float* rmean = (const float*)d_in[5];
    const float* rvar  = (const float*)d_in[6];
    const float* W2    = (const float*)d_in[7];
    const float* b2    = (const float*)d_in[8];
    const float* We    = (const float*)d_in[9];

    float* out = (float*)d_out;                    // [N, A]
    float* ret = out + (size_t)NN * AA;            // [N, E]

    size_t smem = SMEM_FLOATS * sizeof(float);
    static bool attr_set = false;
    if (!attr_set) {
        cudaFuncSetAttribute(moe_fused, cudaFuncAttributeMaxDynamicSharedMemorySize, (int)smem);
        attr_set = true;
    }
    moe_fused<<<GRID, 128, smem>>>(X, W1, b1, gamma, beta, rmean, rvar, W2, b2, We, out, ret);
}

// round 8
// speedup vs baseline: 2.4789x; 2.4789x over previous
#include <cuda_runtime.h>

#define NN 524288
#define ROWS_PB 384
#define GRID ((NN + ROWS_PB - 1) / ROWS_PB)   // 1366
#define DD 64
#define HH 128
#define EE 8
#define AA 18
#define BN_EPS 1e-5f

typedef unsigned long long u64;

__device__ __forceinline__ u64 pk2(float lo, float hi) {
    u64 r; asm("mov.b64 %0,{%1,%2};" : "=l"(r) : "f"(lo), "f"(hi)); return r;
}
__device__ __forceinline__ void upk2(u64 v, float& lo, float& hi) {
    asm("mov.b64 {%0,%1},%2;" : "=f"(lo), "=f"(hi) : "l"(v));
}
__device__ __forceinline__ void ffma2(u64& d, u64 a, u64 b) {
    asm("fma.rn.f32x2 %0,%1,%2,%0;" : "+l"(d) : "l"(a), "l"(b));
}
__device__ __forceinline__ u64 add2(u64 a, u64 b) {
    u64 r; asm("add.rn.f32x2 %0,%1,%2;" : "=l"(r) : "l"(a), "l"(b)); return r;
}

// smem layout (floats):
//   w1s [0, 8192)        W1 row-major [H][D]
//   w2t [8192, 9216)     W2 transposed [H][E]
//   sbs [9216, 9472)     (scale,bias) per j
//   b2s [9472, 9488)
//   wes [9488, 18736)    We flat, stride 1156/expert
//   ints: best[384], order[384], cnt[8], base[8], cnt2[8]
#define WE_STRIDE 1156
#define INT_OFF   18736
#define SMEM_FLOATS (18736 + 384 + 384 + 24)

__global__ __launch_bounds__(128, 2) void moe_fused(
    const float* __restrict__ X,  const float* __restrict__ W1, const float* __restrict__ b1,
    const float* __restrict__ gamma, const float* __restrict__ beta,
    const float* __restrict__ rmean, const float* __restrict__ rvar,
    const float* __restrict__ W2, const float* __restrict__ b2, const float* __restrict__ We,
    float* __restrict__ out, float* __restrict__ ret)
{
    extern __shared__ float sm[];
    float* w1s = sm;
    float* w2t = sm + 8192;
    float* sbs = sm + 9216;
    float* b2s = sm + 9472;
    float* wes = sm + 9488;
    int* best_s  = (int*)(sm + INT_OFF);          // [384]
    int* order_s = (int*)(sm + INT_OFF + 384);    // [384]
    int* cnt_s   = (int*)(sm + INT_OFF + 768);    // [8]
    int* base_s  = (int*)(sm + INT_OFF + 776);    // [8]
    int* cnt2_s  = (int*)(sm + INT_OFF + 784);    // [8]

    const int tid = threadIdx.x;

    // ---- stage weights (128 threads) ----
    {   const float4* src = (const float4*)W1;
        float4* dst = (float4*)w1s;
        #pragma unroll
        for (int i = 0; i < 16; i++) dst[tid + 128 * i] = src[tid + 128 * i];
    }
    {   const float4* src = (const float4*)We;
        float4* dst = (float4*)wes;
        #pragma unroll
        for (int i = 0; i < 18; i++) {
            int idx = tid + 128 * i;
            int e = idx / 288, r = idx % 288;
            dst[e * (WE_STRIDE / 4) + r] = src[idx];
        }
    }
    #pragma unroll
    for (int i = 0; i < 8; i++) {
        int idx = tid + 128 * i;
        int j = idx >> 3, e = idx & 7;
        w2t[idx] = W2[e * HH + j];
    }
    {
        int j = tid;
        float s = gamma[j] * rsqrtf(rvar[j] + BN_EPS);
        sbs[2 * j]     = s;
        sbs[2 * j + 1] = s * (b1[j] - rmean[j]) + beta[j];
    }
    if (tid < EE) { b2s[tid] = b2[tid]; cnt_s[tid] = 0; cnt2_s[tid] = 0; }
    __syncthreads();

    const int row0 = blockIdx.x * ROWS_PB;
    const int base = row0 + tid;
    int rowi[3];
    bool valid[3];
    #pragma unroll
    for (int rr = 0; rr < 3; rr++) {
        int r = base + rr * 128;
        valid[rr] = (r < NN);
        rowi[rr] = valid[rr] ? r : (NN - 1);
    }

    // ---- x for 3 rows in regs ----
    u64 xp0[32], xp1[32], xp2[32];
    {
        const ulonglong2* p0 = (const ulonglong2*)(X + (size_t)rowi[0] * DD);
        const ulonglong2* p1 = (const ulonglong2*)(X + (size_t)rowi[1] * DD);
        const ulonglong2* p2 = (const ulonglong2*)(X + (size_t)rowi[2] * DD);
        #pragma unroll
        for (int i = 0; i < 16; i++) {
            ulonglong2 t0 = p0[i]; xp0[2 * i] = t0.x; xp0[2 * i + 1] = t0.y;
            ulonglong2 t1 = p1[i]; xp1[2 * i] = t1.x; xp1[2 * i + 1] = t1.y;
            ulonglong2 t2 = p2[i]; xp2[2 * i] = t2.x; xp2[2 * i + 1] = t2.y;
        }
    }

    const u64 Z = pk2(0.f, 0.f);

    u64 lg0[4], lg1[4], lg2[4];
    #pragma unroll
    for (int k = 0; k < 4; k++) {
        u64 b2p = pk2(b2s[2 * k], b2s[2 * k + 1]);
        lg0[k] = b2p; lg1[k] = b2p; lg2[k] = b2p;
    }

    // ---- gating: uniform W1 load feeds 3 rows ----
    #pragma unroll 1
    for (int j = 0; j < HH; j++) {
        const ulonglong2* pw = (const ulonglong2*)(w1s + j * DD);
        u64 a0 = Z, a1 = Z, c0 = Z, c1 = Z, d0 = Z, d1 = Z;
        #pragma unroll
        for (int i = 0; i < 16; i++) {
            ulonglong2 w = pw[i];
            ffma2(a0, w.x, xp0[2 * i]);
            ffma2(c0, w.x, xp1[2 * i]);
            ffma2(d0, w.x, xp2[2 * i]);
            ffma2(a1, w.y, xp0[2 * i + 1]);
            ffma2(c1, w.y, xp1[2 * i + 1]);
            ffma2(d1, w.y, xp2[2 * i + 1]);
        }
        u64 s0 = add2(a0, a1), s1 = add2(c0, c1), s2 = add2(d0, d1);
        float e0, f0, e1, f1, e2, f2;
        upk2(s0, e0, f0); upk2(s1, e1, f1); upk2(s2, e2, f2);
        float dot0 = e0 + f0, dot1 = e1 + f1, dot2 = e2 + f2;

        float2 sb = ((const float2*)sbs)[j];
        float y0 = fmaxf(fmaf(sb.x, dot0, sb.y), 0.f);
        float y1 = fmaxf(fmaf(sb.x, dot1, sb.y), 0.f);
        float y2 = fmaxf(fmaf(sb.x, dot2, sb.y), 0.f);
        u64 yb0 = pk2(y0, y0), yb1 = pk2(y1, y1), yb2 = pk2(y2, y2);

        const ulonglong2* pw2 = (const ulonglong2*)(w2t + j * EE);
        ulonglong2 q0 = pw2[0], q1 = pw2[1];
        ffma2(lg0[0], q0.x, yb0);
        ffma2(lg1[0], q0.x, yb1);
        ffma2(lg2[0], q0.x, yb2);
        ffma2(lg0[1], q0.y, yb0);
        ffma2(lg1[1], q0.y, yb1);
        ffma2(lg2[1], q0.y, yb2);
        ffma2(lg0[2], q1.x, yb0);
        ffma2(lg1[2], q1.x, yb1);
        ffma2(lg2[2], q1.x, yb2);
        ffma2(lg0[3], q1.y, yb0);
        ffma2(lg1[3], q1.y, yb1);
        ffma2(lg2[3], q1.y, yb2);
    }

    // ---- argmax + one-hot + bucket counts ----
    #pragma unroll 1
    for (int rr = 0; rr < 3; rr++) {
        if (!valid[rr]) continue;
        const u64* lg = (rr == 0) ? lg0 : (rr == 1) ? lg1 : lg2;
        const int row = rowi[rr];

        float lf[8];
        upk2(lg[0], lf[0], lf[1]);
        upk2(lg[1], lf[2], lf[3]);
        upk2(lg[2], lf[4], lf[5]);
        upk2(lg[3], lf[6], lf[7]);
        int best = 0; float bv = lf[0];
        #pragma unroll
        for (int e = 1; e < 8; e++) if (lf[e] > bv) { bv = lf[e]; best = e; }

        float rv[8];
        #pragma unroll
        for (int e = 0; e < 8; e++) rv[e] = (e == best) ? 1.0f : 0.0f;
        float4* pr = (float4*)(ret + (size_t)row * EE);
        pr[0] = make_float4(rv[0], rv[1], rv[2], rv[3]);
        pr[1] = make_float4(rv[4], rv[5], rv[6], rv[7]);

        best_s[tid + rr * 128] = best;
        atomicAdd(&cnt_s[best], 1);
    }
    __syncthreads();

    int vcount;
    if (tid == 0) {
        int acc0 = 0;
        #pragma unroll
        for (int e = 0; e < 8; e++) { base_s[e] = acc0; acc0 += cnt_s[e]; }
    }
    __syncthreads();
    vcount = base_s[7] + cnt_s[7];

    #pragma unroll 1
    for (int rr = 0; rr < 3; rr++) {
        if (!valid[rr]) continue;
        int lrow = tid + rr * 128;
        int e = best_s[lrow];
        int pos = atomicAdd(&cnt2_s[e], 1);
        order_s[base_s[e] + pos] = lrow;
    }
    __syncthreads();

    // ---- expert GEMV over expert-sorted rows (uniform We loads) ----
    #pragma unroll 1
    for (int rr = 0; rr < 3; rr++) {
        int p = tid + rr * 128;
        if (p >= vcount) continue;
        int lrow = order_s[p];
        int best = best_s[lrow];
        int grow = row0 + lrow;

        // reload x from global (L2-resident)
        u64 xq[32];
        const ulonglong2* pg = (const ulonglong2*)(X + (size_t)grow * DD);
        #pragma unroll
        for (int i = 0; i < 16; i++) {
            ulonglong2 t = pg[i];
            xq[2 * i] = t.x; xq[2 * i + 1] = t.y;
        }

        const ulonglong2* pe = (const ulonglong2*)(wes + best * WE_STRIDE);
        float* orow = out + (size_t)grow * AA;
        #pragma unroll
        for (int a = 0; a < AA; a++) {
            u64 a0 = Z, a1 = Z, a2 = Z, a3 = Z;
            #pragma unroll
            for (int m = 0; m < 8; m++) {
                ulonglong2 w = pe[a * 16 + 2 * m];
                ulonglong2 v = pe[a * 16 + 2 * m + 1];
                ffma2(a0, w.x, xq[4 * m + 0]);
                ffma2(a1, w.y, xq[4 * m + 1]);
                ffma2(a2, v.x, xq[4 * m + 2]);
                ffma2(a3, v.y, xq[4 * m + 3]);
            }
            u64 s = add2(add2(a0, a1), add2(a2, a3));
            float lo, hi; upk2(s, lo, hi);
            orow[a] = lo + hi;
        }
    }
}

extern "C" void kernel_launch(void* const* d_in, const int* in_sizes, int n_in,
                              void* d_out, int out_size) {
    const float* X     = (const float*)d_in[0];
    const float* W1    = (const float*)d_in[1];
    const float* b1    = (const float*)d_in[2];
    const float* gamma = (const float*)d_in[3];
    const float* beta  = (const float*)d_in[4];
    const float* rmean = (const float*)d_in[5];
    const float* rvar  = (const float*)d_in[6];
    const float* W2    = (const float*)d_in[7];
    const float* b2    = (const float*)d_in[8];
    const float* We    = (const float*)d_in[9];

    float* out = (float*)d_out;                    // [N, A]
    float* ret = out + (size_t)NN * AA;            // [N, E]

    size_t smem = SMEM_FLOATS * sizeof(float);
    static bool attr_set = false;
    if (!attr_set) {
        cudaFuncSetAttribute(moe_fused, cudaFuncAttributeMaxDynamicSharedMemorySize, (int)smem);
        attr_set = true;
    }
    moe_fused<<<GRID, 128, smem>>>(X, W1, b1, gamma, beta, rmean, rvar, W2, b2, We, out, ret);
}